// round 4
// baseline (speedup 1.0000x reference)
#include <cuda_runtime.h>
#include <cstdint>

#define T_STEPS 512

// Scratch (allocation-free rule: __device__ globals)
// proj[bucket][lane] = (Pi*0.5, Pf*0.5, Pc*1.0, Po*0.5)  (0.5 = sigmoid-via-tanh prescale)
__device__ __align__(16) float g_proj2[4096 * 32 * 4];
// Rpack: ull at ((c*16 + j)*32 + lane) = (R[2j][col]*s_c, R[2j+1][col]*s_c), col = c*32+lane
__device__ __align__(16) unsigned long long g_R[4 * 16 * 32];

// ---------- packed f32x2 helpers ----------
__device__ __forceinline__ void fma2(unsigned long long& acc, unsigned long long a, unsigned long long b) {
    asm("fma.rn.f32x2 %0, %1, %2, %0;" : "+l"(acc) : "l"(a), "l"(b));
}
__device__ __forceinline__ void unpk2(unsigned long long v, float& lo, float& hi) {
    asm("mov.b64 {%0, %1}, %2;" : "=f"(lo), "=f"(hi) : "l"(v));
}
// ---------- MUFU tanh (sm_75+) ----------
__device__ __forceinline__ float ftanh(float x) {
    float y; asm("tanh.approx.f32 %0, %1;" : "=f"(y) : "f"(x)); return y;
}

// ---------- merged prep ----------
__global__ void prep_all(const float* __restrict__ emb, const float* __restrict__ K,
                         const float* __restrict__ R, int nbuckets) {
    int idx = blockIdx.x * blockDim.x + threadIdx.x;
    // pack rec_kernel: 2048 entries (c, j, lane)
    if (idx < 4 * 16 * 32) {
        int lane = idx & 31, j = (idx >> 5) & 15, c = idx >> 9;
        int col = c * 32 + lane;
        float s = (c == 2) ? 1.0f : 0.5f;
        float lo = R[(2 * j) * 128 + col] * s;
        float hi = R[(2 * j + 1) * 128 + col] * s;
        unsigned long long v;
        asm("mov.b64 %0, {%1, %2};" : "=l"(v) : "f"(lo), "f"(hi));
        g_R[idx] = v;
    }
    // per-bucket projection table
    int id = idx >> 5, l = idx & 31;
    if (id >= nbuckets) return;
    float a = 0.f, b = 0.f, c = 0.f, d = 0.f;
#pragma unroll
    for (int e = 0; e < 16; e++) {
        float xv = emb[id * 16 + e];
        const float* kr = K + e * 128 + l;
        a = fmaf(xv, kr[0],  a);
        b = fmaf(xv, kr[32], b);
        c = fmaf(xv, kr[64], c);
        d = fmaf(xv, kr[96], d);
    }
    *(float4*)&g_proj2[idx * 4] = make_float4(a * 0.5f, b * 0.5f, c, d * 0.5f);
}

// ---------- main: warp handles TWO batch rows; weights shared in registers ----------
__global__ __launch_bounds__(128, 2) void lstm_main(
    const int* __restrict__ ids,
    const float* __restrict__ w1, const float* __restrict__ b1,
    const float* __restrict__ w2, const float* __restrict__ b2,
    float* __restrict__ out, int B)
{
    __shared__ __align__(16) float hb[4][2][2][32];   // [warp][batch][buf][j]
    const int w = threadIdx.x >> 5;
    const int lane = threadIdx.x & 31;
    const int b0 = blockIdx.x * 8 + w;        // first batch row
    const int b1r = b0 + 4;                   // second batch row
    if (b0 >= B) return;                      // uniform per warp

    // recurrent weights (shared between both batches): 4 owned cols x 16 j-pairs
    unsigned long long RW[4][16];
#pragma unroll
    for (int c = 0; c < 4; c++)
#pragma unroll
        for (int j = 0; j < 16; j++)
            RW[c][j] = g_R[(c * 16 + j) * 32 + lane];

    const float4* Pp = (const float4*)g_proj2;
    const int* idrow0 = ids + b0  * T_STEPS;
    const int* idrow1 = ids + b1r * T_STEPS;
    int idreg0 = idrow0[lane];
    int idreg1 = idrow1[lane];
    float4 pA = Pp[__shfl_sync(0xffffffffu, idreg0, 0) * 32 + lane];
    float4 pB = Pp[__shfl_sync(0xffffffffu, idreg1, 0) * 32 + lane];

    hb[w][0][0][lane] = 0.f;
    hb[w][1][0][lane] = 0.f;
    __syncwarp();

    float cA = 0.f, cB = 0.f;
    for (int t = 0; t < T_STEPS; t++) {
        // prefetch proj for step t+1 (hidden behind this step's math)
        int tn = t + 1;
        if (((tn & 31) == 0) && (tn < T_STEPS)) {
            idreg0 = idrow0[tn + lane];
            idreg1 = idrow1[tn + lane];
        }
        float4 pnA = Pp[__shfl_sync(0xffffffffu, idreg0, tn & 31) * 32 + lane];
        float4 pnB = Pp[__shfl_sync(0xffffffffu, idreg1, tn & 31) * 32 + lane];

        unsigned long long a0 = 0ull, a1 = 0ull, a2 = 0ull, a3 = 0ull;
        unsigned long long d0 = 0ull, d1 = 0ull, d2 = 0ull, d3 = 0ull;
        const ulonglong2* hpA = (const ulonglong2*)&hb[w][0][t & 1][0];
        const ulonglong2* hpB = (const ulonglong2*)&hb[w][1][t & 1][0];
#pragma unroll
        for (int k = 0; k < 8; k++) {
            ulonglong2 hvA = hpA[k];          // broadcast LDS.128: (h4k,h4k+1),(h4k+2,h4k+3)
            ulonglong2 hvB = hpB[k];
            fma2(a0, RW[0][2 * k], hvA.x);
            fma2(a1, RW[1][2 * k], hvA.x);
            fma2(a2, RW[2][2 * k], hvA.x);
            fma2(a3, RW[3][2 * k], hvA.x);
            fma2(d0, RW[0][2 * k], hvB.x);
            fma2(d1, RW[1][2 * k], hvB.x);
            fma2(d2, RW[2][2 * k], hvB.x);
            fma2(d3, RW[3][2 * k], hvB.x);
            fma2(a0, RW[0][2 * k + 1], hvA.y);
            fma2(a1, RW[1][2 * k + 1], hvA.y);
            fma2(a2, RW[2][2 * k + 1], hvA.y);
            fma2(a3, RW[3][2 * k + 1], hvA.y);
            fma2(d0, RW[0][2 * k + 1], hvB.y);
            fma2(d1, RW[1][2 * k + 1], hvB.y);
            fma2(d2, RW[2][2 * k + 1], hvB.y);
            fma2(d3, RW[3][2 * k + 1], hvB.y);
        }
        // batch A tail
        float e0, o0, e1, o1, e2, o2, e3, o3;
        unpk2(a0, e0, o0); unpk2(a1, e1, o1); unpk2(a2, e2, o2); unpk2(a3, e3, o3);
        float ziA = pA.x + e0 + o0, zfA = pA.y + e1 + o1;
        float zcA = pA.z + e2 + o2, zoA = pA.w + e3 + o3;
        // batch B tail (independent — ILP 2 through MUFU chain)
        unpk2(d0, e0, o0); unpk2(d1, e1, o1); unpk2(d2, e2, o2); unpk2(d3, e3, o3);
        float ziB = pB.x + e0 + o0, zfB = pB.y + e1 + o1;
        float zcB = pB.z + e2 + o2, zoB = pB.w + e3 + o3;

        float igA = fmaf(ftanh(ziA), 0.5f, 0.5f);
        float igB = fmaf(ftanh(ziB), 0.5f, 0.5f);
        float fgA = fmaf(ftanh(zfA), 0.5f, 0.5f);
        float fgB = fmaf(ftanh(zfB), 0.5f, 0.5f);
        float ogA = fmaf(ftanh(zoA), 0.5f, 0.5f);
        float ogB = fmaf(ftanh(zoB), 0.5f, 0.5f);
        float ggA = ftanh(zcA);
        float ggB = ftanh(zcB);
        cA = fmaf(fgA, cA, igA * ggA);
        cB = fmaf(fgB, cB, igB * ggB);
        float hA = ogA * ftanh(cA);
        float hB = ogB * ftanh(cB);

        hb[w][0][tn & 1][lane] = hA;
        hb[w][1][tn & 1][lane] = hB;
        __syncwarp();
        pA = pnA;
        pB = pnB;
    }

    // head: y = relu(h @ w1 + b1) @ w2 + b2, for both batch rows
    float w2l = w2[lane];
    float b1l = b1[lane];
#pragma unroll
    for (int q = 0; q < 2; q++) {
        float s = b1l;
#pragma unroll
        for (int l = 0; l < 32; l++)
            s = fmaf(hb[w][q][0][l], w1[l * 32 + lane], s);
        float r = fmaxf(s, 0.f) * w2l;
#pragma unroll
        for (int off = 16; off; off >>= 1)
            r += __shfl_xor_sync(0xffffffffu, r, off);
        if (lane == 0) out[q ? b1r : b0] = r + b2[0];
    }
}

extern "C" void kernel_launch(void* const* d_in, const int* in_sizes, int n_in,
                              void* d_out, int out_size)
{
    const int*   ids  = (const int*)d_in[0];
    const float* emb  = (const float*)d_in[1];
    const float* kern = (const float*)d_in[2];
    const float* rec  = (const float*)d_in[3];
    const float* w1   = (const float*)d_in[4];
    const float* b1   = (const float*)d_in[5];
    const float* w2   = (const float*)d_in[6];
    const float* b2   = (const float*)d_in[7];

    int B = in_sizes[0] / T_STEPS;
    int nbuckets = in_sizes[1] / 16;
    if (nbuckets > 4096) nbuckets = 4096;

    int prep_threads = nbuckets * 32;
    if (prep_threads < 2048) prep_threads = 2048;
    prep_all<<<(prep_threads + 127) / 128, 128>>>(emb, kern, rec, nbuckets);
    lstm_main<<<(B + 7) / 8, 128>>>(ids, w1, b1, w2, b2, (float*)d_out, B);
}